// round 1
// baseline (speedup 1.0000x reference)
#include <cuda_runtime.h>

// LearnedBFGSSolver: T=12 BFGS rank-2 inverse-Hessian updates, 256 (b,e) pairs,
// N=192. Low-rank reformulation: H_T = H0 + sum_k rank-2 terms; only vectors
// (s_k, u_k=H_k y_k, v_k=H_k^T y_k) are carried through the recursion.
// One CTA per pair. H0 lives in padded SMEM; all heavy phases are FMA-bound.

#define NN 192
#define TT 12
#define BE 256          // B*E = 8*32
#define NPAD 196        // pad for conflict-free row (float4) + column access
#define NTHREADS 256
#define NWARPS 8

struct Smem {
    float H0[NN * NPAD];     // 150,528 B
    float S[TT][NN];         // steps
    float Y[TT][NN];         // delta_grads
    float U[TT][NN];         // u_k = H_k y_k   (starts as H0 y_k)
    float V[TT][NN];         // v_k = H_k^T y_k (starts as H0^T y_k)
    float A[TT][NN];         // A[k][j] = c1_k s_kj - c2_k v_kj
    float Bc[TT][NN];        // B[k][j] = -c2_k s_kj
    float d1[TT], d2[TT], d3[TT];
    float c1[TT], c2[TT];
};

__global__ void __launch_bounds__(NTHREADS, 1)
bfgs_kernel(const float* __restrict__ H0g,
            const float* __restrict__ steps,
            const float* __restrict__ dgs,
            float* __restrict__ out)
{
    extern __shared__ float smem_raw[];
    Smem* sm = reinterpret_cast<Smem*>(smem_raw);
    const int tid = threadIdx.x;
    const int be  = blockIdx.x;
    const int wid = tid >> 5;
    const int lane = tid & 31;

    // ---- Load H0 (broadcast across CTAs, L2-resident) into padded SMEM ----
    for (int idx = tid; idx < NN * NN / 4; idx += NTHREADS) {
        int e = idx * 4;
        int r = e / NN, c = e % NN;
        float4 v = reinterpret_cast<const float4*>(H0g)[idx];
        *reinterpret_cast<float4*>(&sm->H0[r * NPAD + c]) = v;
    }
    // ---- Load this pair's s_t, y_t vectors ----
    for (int idx = tid; idx < TT * NN / 4; idx += NTHREADS) {
        int e = idx * 4;
        int t = e / NN, i = e % NN;
        float4 sv = *reinterpret_cast<const float4*>(&steps[(size_t)(t * BE + be) * NN + i]);
        float4 yv = *reinterpret_cast<const float4*>(&dgs[(size_t)(t * BE + be) * NN + i]);
        *reinterpret_cast<float4*>(&sm->S[t][i]) = sv;
        *reinterpret_cast<float4*>(&sm->Y[t][i]) = yv;
    }
    __syncthreads();

    // ---- Phase 1: one pass over H0 computes U[t] = H0 @ y_t and
    //      V[t] = H0^T @ y_t for ALL t (24 FMA per H0 element). ----
    if (tid < NN) {
        const int i = tid;
        // p[t] = row i of H0 dot y_t   (float4 row loads, conflict-free)
        float p[TT];
        #pragma unroll
        for (int t = 0; t < TT; t++) p[t] = 0.f;
        for (int j = 0; j < NN; j += 4) {
            float4 h = *reinterpret_cast<float4*>(&sm->H0[i * NPAD + j]);
            #pragma unroll
            for (int t = 0; t < TT; t++) {
                float4 y = *reinterpret_cast<float4*>(&sm->Y[t][j]);
                p[t] += h.x * y.x + h.y * y.y + h.z * y.z + h.w * y.w;
            }
        }
        #pragma unroll
        for (int t = 0; t < TT; t++) sm->U[t][i] = p[t];

        // q[t] = column i of H0 dot y_t (scalar column loads, conflict-free)
        float q[TT];
        #pragma unroll
        for (int t = 0; t < TT; t++) q[t] = 0.f;
        for (int jj = 0; jj < NN; jj += 4) {
            float h0 = sm->H0[(jj + 0) * NPAD + i];
            float h1 = sm->H0[(jj + 1) * NPAD + i];
            float h2 = sm->H0[(jj + 2) * NPAD + i];
            float h3 = sm->H0[(jj + 3) * NPAD + i];
            #pragma unroll
            for (int t = 0; t < TT; t++) {
                float4 y = *reinterpret_cast<float4*>(&sm->Y[t][jj]);
                q[t] += h0 * y.x + h1 * y.y + h2 * y.z + h3 * y.w;
            }
        }
        #pragma unroll
        for (int t = 0; t < TT; t++) sm->V[t][i] = q[t];
    }
    __syncthreads();

    // ---- Phase 2: sequential recursion over t (cheap: O(T^2) vector ops) ----
    for (int t = 0; t < TT; t++) {
        // Dots: d1[k]=s_k.y_t (incl. k==t -> sdot), d2[k]=v_k.y_t, d3[k]=u_k.y_t
        for (int k = wid; k <= t; k += NWARPS) {
            float a1 = 0.f, a2 = 0.f, a3 = 0.f;
            for (int e = lane; e < NN; e += 32) {
                float yv = sm->Y[t][e];
                a1 += sm->S[k][e] * yv;
                if (k < t) {
                    a2 += sm->V[k][e] * yv;
                    a3 += sm->U[k][e] * yv;
                }
            }
            #pragma unroll
            for (int o = 16; o; o >>= 1) {
                a1 += __shfl_xor_sync(0xFFFFFFFFu, a1, o);
                a2 += __shfl_xor_sync(0xFFFFFFFFu, a2, o);
                a3 += __shfl_xor_sync(0xFFFFFFFFu, a3, o);
            }
            if (lane == 0) {
                sm->d1[k] = a1;
                if (k < t) { sm->d2[k] = a2; sm->d3[k] = a3; }
            }
        }
        __syncthreads();

        // Low-rank correction: u_t += sum_{k<t} W_k y_t ; v_t += sum W_k^T y_t
        if (tid < NN) {
            const int i = tid;
            float u = sm->U[t][i];
            float v = sm->V[t][i];
            for (int k = 0; k < t; k++) {
                float c1k = sm->c1[k], c2k = sm->c2[k];
                float dd1 = sm->d1[k];
                float b   = -c2k * dd1;
                float au  = c1k * dd1 - c2k * sm->d2[k];
                float av  = c1k * dd1 - c2k * sm->d3[k];
                float sk = sm->S[k][i];
                u += au * sk + b * sm->U[k][i];
                v += av * sk + b * sm->V[k][i];
            }
            sm->U[t][i] = u;
            sm->V[t][i] = v;
        }
        __syncthreads();

        // yHy = y_t . u_t ; then scalars c1[t], c2[t] (masked if sdot == 0)
        if (wid == 0) {
            float a = 0.f;
            for (int e = lane; e < NN; e += 32) a += sm->Y[t][e] * sm->U[t][e];
            #pragma unroll
            for (int o = 16; o; o >>= 1) a += __shfl_xor_sync(0xFFFFFFFFu, a, o);
            if (lane == 0) {
                float sdot = sm->d1[t];
                if (sdot != 0.0f) {
                    float ic = 1.0f / sdot;
                    sm->c2[t] = ic;
                    sm->c1[t] = (sdot + a) * ic * ic;
                } else {
                    sm->c1[t] = 0.0f;
                    sm->c2[t] = 0.0f;
                }
            }
        }
        __syncthreads();
    }

    // ---- Phase 3a: epilogue coefficient vectors ----
    for (int idx = tid; idx < TT * NN; idx += NTHREADS) {
        int k = idx / NN, j = idx % NN;
        float c1k = sm->c1[k], c2k = sm->c2[k];
        sm->A[k][j]  = c1k * sm->S[k][j] - c2k * sm->V[k][j];
        sm->Bc[k][j] = -c2k * sm->S[k][j];
    }
    __syncthreads();

    // ---- Phase 3b: materialize H_T = H0 + S*A + U*B (rank-24 update),
    //      register-tiled 4 rows x 8 cols. 48 i-tiles * 24 j-tiles = 1152. ----
    float* outbase = out + (size_t)be * NN * NN;
    for (int tile = tid; tile < 48 * 24; tile += NTHREADS) {
        const int ti = (tile / 24) * 4;
        const int tj = (tile % 24) * 8;
        float acc[4][8];
        #pragma unroll
        for (int r = 0; r < 4; r++) {
            float4 h0 = *reinterpret_cast<float4*>(&sm->H0[(ti + r) * NPAD + tj]);
            float4 h1 = *reinterpret_cast<float4*>(&sm->H0[(ti + r) * NPAD + tj + 4]);
            acc[r][0] = h0.x; acc[r][1] = h0.y; acc[r][2] = h0.z; acc[r][3] = h0.w;
            acc[r][4] = h1.x; acc[r][5] = h1.y; acc[r][6] = h1.z; acc[r][7] = h1.w;
        }
        #pragma unroll
        for (int k = 0; k < TT; k++) {
            float4 s4 = *reinterpret_cast<float4*>(&sm->S[k][ti]);
            float4 u4 = *reinterpret_cast<float4*>(&sm->U[k][ti]);
            float4 a0 = *reinterpret_cast<float4*>(&sm->A[k][tj]);
            float4 a1 = *reinterpret_cast<float4*>(&sm->A[k][tj + 4]);
            float4 b0 = *reinterpret_cast<float4*>(&sm->Bc[k][tj]);
            float4 b1 = *reinterpret_cast<float4*>(&sm->Bc[k][tj + 4]);
            float si[4] = {s4.x, s4.y, s4.z, s4.w};
            float ui[4] = {u4.x, u4.y, u4.z, u4.w};
            float aj[8] = {a0.x, a0.y, a0.z, a0.w, a1.x, a1.y, a1.z, a1.w};
            float bj[8] = {b0.x, b0.y, b0.z, b0.w, b1.x, b1.y, b1.z, b1.w};
            #pragma unroll
            for (int r = 0; r < 4; r++)
                #pragma unroll
                for (int c = 0; c < 8; c++)
                    acc[r][c] += si[r] * aj[c] + ui[r] * bj[c];
        }
        #pragma unroll
        for (int r = 0; r < 4; r++) {
            float4 o0 = make_float4(acc[r][0], acc[r][1], acc[r][2], acc[r][3]);
            float4 o1 = make_float4(acc[r][4], acc[r][5], acc[r][6], acc[r][7]);
            *reinterpret_cast<float4*>(&outbase[(size_t)(ti + r) * NN + tj])     = o0;
            *reinterpret_cast<float4*>(&outbase[(size_t)(ti + r) * NN + tj + 4]) = o1;
        }
    }
}

extern "C" void kernel_launch(void* const* d_in, const int* in_sizes, int n_in,
                              void* d_out, int out_size) {
    const float* H0    = (const float*)d_in[0];   // inv_hessian [192,192]
    const float* steps = (const float*)d_in[1];   // [12,8,32,192]
    const float* dgs   = (const float*)d_in[2];   // [12,8,32,192]
    float* out = (float*)d_out;                   // [8,32,192,192]

    int smem_bytes = (int)sizeof(Smem);
    cudaFuncSetAttribute(bfgs_kernel,
                         cudaFuncAttributeMaxDynamicSharedMemorySize, smem_bytes);
    bfgs_kernel<<<BE, NTHREADS, smem_bytes>>>(H0, steps, dgs, out);
}

// round 2
// speedup vs baseline: 1.3547x; 1.3547x over previous
#include <cuda_runtime.h>

// LearnedBFGSSolver: T=12 BFGS rank-2 updates, 256 (b,e) pairs, N=192.
// Low-rank form: carry only s_k, u_k=H_k y_k, v_k=H_k^T y_k through the
// recursion; final H = H0 + S*A + U*B (rank-24). H0 stays in L2 (not SMEM)
// so 2 CTAs/SM fit -> single wave. f32x2 packed FMA throughout.

#define NN 192
#define TT 12
#define BE 256
#define NTHREADS 256
#define NWARPS 8

typedef unsigned long long u64;

__device__ float g_H0T[NN * NN];   // transposed copy of inv_hessian

__device__ __forceinline__ u64 fma2(u64 a, u64 b, u64 c) {
    u64 d; asm("fma.rn.f32x2 %0, %1, %2, %3;" : "=l"(d) : "l"(a), "l"(b), "l"(c));
    return d;
}
__device__ __forceinline__ u64 pack2(float lo, float hi) {
    u64 d; asm("mov.b64 %0, {%1, %2};" : "=l"(d) : "f"(lo), "f"(hi));
    return d;
}
__device__ __forceinline__ void unpack2(u64 v, float& lo, float& hi) {
    asm("mov.b64 {%0, %1}, %2;" : "=f"(lo), "=f"(hi) : "l"(v));
}

struct Smem {
    float S[TT][NN];
    float Y[TT][NN];
    float U[TT][NN];
    float V[TT][NN];
    float A[TT][NN];     // A[k][j] = c1_k s_kj - c2_k v_kj
    float Bc[TT][NN];    // B[k][j] = -c2_k s_kj
    u64   Yp[NN][TT / 2];  // Yp[j][t2] = (Y[2t2][j], Y[2t2+1][j])
    float d1[TT], d2[TT], d3[TT], c1[TT], c2[TT];
};

// ---- tiled transpose of H0 into g_H0T (both sides coalesced) ----
__global__ void transpose_kernel(const float* __restrict__ H0g) {
    __shared__ float tile[32][33];
    int bx = blockIdx.x % 6, by = blockIdx.x / 6;
    int x = bx * 32 + threadIdx.x;
    int y = by * 32 + threadIdx.y;
    tile[threadIdx.y][threadIdx.x] = H0g[y * NN + x];
    __syncthreads();
    int xo = by * 32 + threadIdx.x;
    int yo = bx * 32 + threadIdx.y;
    g_H0T[yo * NN + xo] = tile[threadIdx.x][threadIdx.y];
}

__global__ void __launch_bounds__(NTHREADS, 2)
bfgs_kernel(const float* __restrict__ H0g,
            const float* __restrict__ steps,
            const float* __restrict__ dgs,
            float* __restrict__ out)
{
    extern __shared__ float smem_raw[];
    Smem* sm = reinterpret_cast<Smem*>(smem_raw);
    const int tid = threadIdx.x;
    const int be  = blockIdx.x;
    const int wid = tid >> 5;
    const int lane = tid & 31;

    // ---- Load this pair's s_t, y_t vectors ----
    for (int idx = tid; idx < TT * NN / 4; idx += NTHREADS) {
        int e = idx * 4;
        int t = e / NN, i = e % NN;
        float4 sv = *reinterpret_cast<const float4*>(&steps[(size_t)(t * BE + be) * NN + i]);
        float4 yv = *reinterpret_cast<const float4*>(&dgs[(size_t)(t * BE + be) * NN + i]);
        *reinterpret_cast<float4*>(&sm->S[t][i]) = sv;
        *reinterpret_cast<float4*>(&sm->Y[t][i]) = yv;
    }
    __syncthreads();

    // ---- Pack Y into t-pairs for f32x2 ----
    if (tid < NN) {
        #pragma unroll
        for (int t2 = 0; t2 < TT / 2; t2++)
            sm->Yp[tid][t2] = pack2(sm->Y[2 * t2][tid], sm->Y[2 * t2 + 1][tid]);
    }
    __syncthreads();

    // ---- Phase 1: U[t] = H0 y_t, V[t] = H0^T y_t for all t, one coalesced
    //      pass over H0 and H0T (thread i <-> column i). ----
    if (tid < NN) {
        const int i = tid;
        u64 p2[TT / 2], q2[TT / 2];
        #pragma unroll
        for (int t2 = 0; t2 < TT / 2; t2++) { p2[t2] = 0ull; q2[t2] = 0ull; }
        const float* __restrict__ hTcol = g_H0T + i;   // column i of H0T -> U
        const float* __restrict__ hcol  = H0g  + i;    // column i of H0  -> V
        #pragma unroll 4
        for (int j = 0; j < NN; j++) {
            float hT = __ldg(&hTcol[j * NN]);
            float h  = __ldg(&hcol[j * NN]);
            u64 hT2 = pack2(hT, hT);
            u64 h2  = pack2(h, h);
            #pragma unroll
            for (int t2 = 0; t2 < TT / 2; t2++) {
                u64 y2 = sm->Yp[j][t2];
                p2[t2] = fma2(hT2, y2, p2[t2]);
                q2[t2] = fma2(h2,  y2, q2[t2]);
            }
        }
        #pragma unroll
        for (int t2 = 0; t2 < TT / 2; t2++) {
            unpack2(p2[t2], sm->U[2 * t2][i], sm->U[2 * t2 + 1][i]);
            unpack2(q2[t2], sm->V[2 * t2][i], sm->V[2 * t2 + 1][i]);
        }
    }
    __syncthreads();

    // ---- Phase 2: sequential recursion over t ----
    for (int t = 0; t < TT; t++) {
        for (int k = wid; k <= t; k += NWARPS) {
            float a1 = 0.f, a2 = 0.f, a3 = 0.f;
            for (int e = lane; e < NN; e += 32) {
                float yv = sm->Y[t][e];
                a1 += sm->S[k][e] * yv;
                if (k < t) {
                    a2 += sm->V[k][e] * yv;
                    a3 += sm->U[k][e] * yv;
                }
            }
            #pragma unroll
            for (int o = 16; o; o >>= 1) {
                a1 += __shfl_xor_sync(0xFFFFFFFFu, a1, o);
                a2 += __shfl_xor_sync(0xFFFFFFFFu, a2, o);
                a3 += __shfl_xor_sync(0xFFFFFFFFu, a3, o);
            }
            if (lane == 0) {
                sm->d1[k] = a1;
                if (k < t) { sm->d2[k] = a2; sm->d3[k] = a3; }
            }
        }
        __syncthreads();

        if (tid < NN) {
            const int i = tid;
            float u = sm->U[t][i];
            float v = sm->V[t][i];
            for (int k = 0; k < t; k++) {
                float c1k = sm->c1[k], c2k = sm->c2[k];
                float dd1 = sm->d1[k];
                float b   = -c2k * dd1;
                float au  = c1k * dd1 - c2k * sm->d2[k];
                float av  = c1k * dd1 - c2k * sm->d3[k];
                float sk  = sm->S[k][i];
                u += au * sk + b * sm->U[k][i];
                v += av * sk + b * sm->V[k][i];
            }
            sm->U[t][i] = u;
            sm->V[t][i] = v;
        }
        __syncthreads();

        if (wid == 0) {
            float a = 0.f;
            for (int e = lane; e < NN; e += 32) a += sm->Y[t][e] * sm->U[t][e];
            #pragma unroll
            for (int o = 16; o; o >>= 1) a += __shfl_xor_sync(0xFFFFFFFFu, a, o);
            if (lane == 0) {
                float sdot = sm->d1[t];
                if (sdot != 0.0f) {
                    float ic = 1.0f / sdot;
                    sm->c2[t] = ic;
                    sm->c1[t] = (sdot + a) * ic * ic;
                } else {
                    sm->c1[t] = 0.0f;
                    sm->c2[t] = 0.0f;
                }
            }
        }
        __syncthreads();
    }

    // ---- Phase 3a: epilogue coefficient vectors ----
    for (int idx = tid; idx < TT * NN; idx += NTHREADS) {
        int k = idx / NN, j = idx % NN;
        float c1k = sm->c1[k], c2k = sm->c2[k];
        sm->A[k][j]  = c1k * sm->S[k][j] - c2k * sm->V[k][j];
        sm->Bc[k][j] = -c2k * sm->S[k][j];
    }
    __syncthreads();

    // ---- Phase 3b: H_T = H0 + S*A + U*B, rank-24, f32x2 packed.
    //      4x8 register tiles; H0 read from L2 (coalesced 32B/thread). ----
    float* outbase = out + (size_t)be * NN * NN;
    for (int tile = tid; tile < 48 * 24; tile += NTHREADS) {
        const int ti = (tile / 24) * 4;
        const int tj = (tile % 24) * 8;
        u64 acc[4][4];
        #pragma unroll
        for (int r = 0; r < 4; r++) {
            ulonglong2 h01 = *reinterpret_cast<const ulonglong2*>(&H0g[(ti + r) * NN + tj]);
            ulonglong2 h23 = *reinterpret_cast<const ulonglong2*>(&H0g[(ti + r) * NN + tj + 4]);
            acc[r][0] = h01.x; acc[r][1] = h01.y;
            acc[r][2] = h23.x; acc[r][3] = h23.y;
        }
        #pragma unroll
        for (int k = 0; k < TT; k++) {
            float4 s4 = *reinterpret_cast<float4*>(&sm->S[k][ti]);
            float4 u4 = *reinterpret_cast<float4*>(&sm->U[k][ti]);
            ulonglong2 a01 = *reinterpret_cast<ulonglong2*>(&sm->A[k][tj]);
            ulonglong2 a23 = *reinterpret_cast<ulonglong2*>(&sm->A[k][tj + 4]);
            ulonglong2 b01 = *reinterpret_cast<ulonglong2*>(&sm->Bc[k][tj]);
            ulonglong2 b23 = *reinterpret_cast<ulonglong2*>(&sm->Bc[k][tj + 4]);
            u64 a2[4] = {a01.x, a01.y, a23.x, a23.y};
            u64 b2[4] = {b01.x, b01.y, b23.x, b23.y};
            u64 s2[4] = {pack2(s4.x, s4.x), pack2(s4.y, s4.y),
                         pack2(s4.z, s4.z), pack2(s4.w, s4.w)};
            u64 u2[4] = {pack2(u4.x, u4.x), pack2(u4.y, u4.y),
                         pack2(u4.z, u4.z), pack2(u4.w, u4.w)};
            #pragma unroll
            for (int r = 0; r < 4; r++)
                #pragma unroll
                for (int c = 0; c < 4; c++) {
                    acc[r][c] = fma2(s2[r], a2[c], acc[r][c]);
                    acc[r][c] = fma2(u2[r], b2[c], acc[r][c]);
                }
        }
        #pragma unroll
        for (int r = 0; r < 4; r++) {
            *reinterpret_cast<ulonglong2*>(&outbase[(size_t)(ti + r) * NN + tj]) =
                make_ulonglong2(acc[r][0], acc[r][1]);
            *reinterpret_cast<ulonglong2*>(&outbase[(size_t)(ti + r) * NN + tj + 4]) =
                make_ulonglong2(acc[r][2], acc[r][3]);
        }
    }
}

extern "C" void kernel_launch(void* const* d_in, const int* in_sizes, int n_in,
                              void* d_out, int out_size) {
    const float* H0    = (const float*)d_in[0];   // inv_hessian [192,192]
    const float* steps = (const float*)d_in[1];   // [12,8,32,192]
    const float* dgs   = (const float*)d_in[2];   // [12,8,32,192]
    float* out = (float*)d_out;                   // [8,32,192,192]

    transpose_kernel<<<36, dim3(32, 32)>>>(H0);

    int smem_bytes = (int)sizeof(Smem);
    cudaFuncSetAttribute(bfgs_kernel,
                         cudaFuncAttributeMaxDynamicSharedMemorySize, smem_bytes);
    bfgs_kernel<<<BE, NTHREADS, smem_bytes>>>(H0, steps, dgs, out);
}